// round 14
// baseline (speedup 1.0000x reference)
#include <cuda_runtime.h>
#include <cuda_bf16.h>
#include <math.h>
#include <stdint.h>

// ---------------- scratch (static device globals; no allocation) ------------
__device__ __nv_bfloat16 g_wqkv[1536 * 512];     // w_qkv bf16
__device__ __nv_bfloat16 g_wproj[512 * 512];     // w_proj bf16
__device__ __nv_bfloat16 g_hT[8 * 1024 * 512];   // groupnorm out [b][t][c]
__device__ __nv_bfloat16 g_qT[64 * 1024 * 64];   // Q [bh][t][c] (pre-scaled 1/8)
__device__ __nv_bfloat16 g_kT[64 * 1024 * 64];   // K [bh][s][c]
__device__ __nv_bfloat16 g_v[64 * 64 * 1024];    // V [bh][c][t]
__device__ __nv_bfloat16 g_aT[8 * 1024 * 512];   // attention out [b][t][c]

__device__ __forceinline__ uint32_t pack_bf16(float lo, float hi) {
    uint32_t r;
    asm("cvt.rn.bf16x2.f32 %0, %1, %2;" : "=r"(r) : "f"(hi), "f"(lo));
    return r;
}
__device__ __forceinline__ uint32_t su32(const void* p) {
    return (uint32_t)__cvta_generic_to_shared(p);
}
__device__ __forceinline__ void cp16(uint32_t dst, const void* src) {
    asm volatile("cp.async.ca.shared.global [%0], [%1], 16;" :: "r"(dst), "l"(src));
}
#define CP_COMMIT() asm volatile("cp.async.commit_group;")
#define CP_WAIT1()  asm volatile("cp.async.wait_group 1;")

#define MMA_BF16(c, a0, a1, a2, a3, b0, b1)                                   \
    asm volatile(                                                             \
        "mma.sync.aligned.m16n8k16.row.col.f32.bf16.bf16.f32 "                \
        "{%0,%1,%2,%3}, {%4,%5,%6,%7}, {%8,%9}, {%0,%1,%2,%3};"               \
        : "+f"((c)[0]), "+f"((c)[1]), "+f"((c)[2]), "+f"((c)[3])              \
        : "r"(a0), "r"(a1), "r"(a2), "r"(a3), "r"(b0), "r"(b1))

#define LDSM_X4(r0, r1, r2, r3, addr)                                         \
    asm volatile("ldmatrix.sync.aligned.m8n8.x4.shared.b16 {%0,%1,%2,%3}, [%4];" \
                 : "=r"(r0), "=r"(r1), "=r"(r2), "=r"(r3) : "r"(addr))
#define LDSM_X2(r0, r1, addr)                                                 \
    asm volatile("ldmatrix.sync.aligned.m8n8.x2.shared.b16 {%0,%1}, [%2];"    \
                 : "=r"(r0), "=r"(r1) : "r"(addr))

// ---------------- fp32 -> bf16 convert (weights) ----------------------------
__global__ void f2bf_kernel(const float* __restrict__ in,
                            __nv_bfloat16* __restrict__ out, int n4) {
    int i = blockIdx.x * 256 + threadIdx.x;
    if (i < n4) {
        float4 v = ((const float4*)in)[i];
        *(uint2*)&out[i * 4] =
            make_uint2(pack_bf16(v.x, v.y), pack_bf16(v.z, v.w));
    }
}

// ---------------- GroupNorm (writes transposed bf16 hT [b][t][c]) -----------
__global__ void groupnorm_t_kernel(const float* __restrict__ x,
                                   const float* __restrict__ gamma,
                                   const float* __restrict__ beta,
                                   __nv_bfloat16* __restrict__ hT) {
    int b = blockIdx.x >> 5;
    int g = blockIdx.x & 31;
    const float* xp = x + ((size_t)b * 512 + g * 16) * 1024;
    int tid = threadIdx.x;

    float s = 0.f, ss = 0.f;
    for (int e = tid; e < 16 * 1024; e += 256) {
        float v = xp[e];
        s += v; ss += v * v;
    }
    __shared__ float rs[256], rss[256];
    __shared__ float Ts[64][20];
    rs[tid] = s; rss[tid] = ss;
    __syncthreads();
    for (int o = 128; o > 0; o >>= 1) {
        if (tid < o) { rs[tid] += rs[tid + o]; rss[tid] += rss[tid + o]; }
        __syncthreads();
    }
    float mean = rs[0] * (1.f / 16384.f);
    float var  = rss[0] * (1.f / 16384.f) - mean * mean;
    float inv  = rsqrtf(var + 1e-5f);

    int cl = tid >> 4;
    int tw4 = (tid & 15) * 4;
    float scale = inv * gamma[g * 16 + cl];
    float shift = beta[g * 16 + cl] - mean * scale;
    __nv_bfloat16* hTb = hT + (size_t)b * 1024 * 512 + g * 16;
    int tr = tid >> 2, q = tid & 3;

    for (int t0 = 0; t0 < 1024; t0 += 64) {
        float4 v = *(const float4*)&xp[cl * 1024 + t0 + tw4];
        Ts[tw4 + 0][cl] = v.x * scale + shift;
        Ts[tw4 + 1][cl] = v.y * scale + shift;
        Ts[tw4 + 2][cl] = v.z * scale + shift;
        Ts[tw4 + 3][cl] = v.w * scale + shift;
        __syncthreads();
        *(uint2*)&hTb[(size_t)(t0 + tr) * 512 + q * 4] =
            make_uint2(pack_bf16(Ts[tr][q * 4 + 0], Ts[tr][q * 4 + 1]),
                       pack_bf16(Ts[tr][q * 4 + 2], Ts[tr][q * 4 + 3]));
        __syncthreads();
    }
}

// ---------------- BF16 GEMM: 64x64 warp tiles, cp.async 3-stage --------------
// Block 128x128, BK=64, 128 threads (4 warps, 2x2), warp tile 64x64.
#define GSTRIDE 72
#define GTILE (128 * GSTRIDE)
extern __shared__ __nv_bfloat16 dyn_smem[];

__global__ __launch_bounds__(128, 2)
void gemm_bf16_async(const __nv_bfloat16* __restrict__ W,
                     const __nv_bfloat16* __restrict__ BT,
                     const float* __restrict__ bias,
                     const float* __restrict__ resid,
                     float* __restrict__ Cout,
                     __nv_bfloat16* __restrict__ qTp,
                     __nv_bfloat16* __restrict__ kTp,
                     __nv_bfloat16* __restrict__ vp,
                     int M, int Kdim) {
    __nv_bfloat16* As = dyn_smem;
    __nv_bfloat16* Bs = dyn_smem + 3 * GTILE;

    int bz = blockIdx.z;
    const __nv_bfloat16* Bp = BT + (size_t)bz * 1024 * Kdim;

    int m0 = blockIdx.y * 128, n0 = blockIdx.x * 128;
    int tid = threadIdx.x;
    int wid = tid >> 5, lane = tid & 31;
    int warp_m = wid >> 1, warp_n = wid & 1;
    int wm0 = warp_m * 64, wn0 = warp_n * 64;
    int gr = lane >> 2, gc = lane & 3;

    int ldr = tid >> 3;          // 0..15 (+i*16)
    int ldc = (tid & 7) * 8;     // 0..56
    uint32_t aU = su32(As), bU = su32(Bs);

    auto prefetch = [&](int kt, int st) {
        const __nv_bfloat16* wsrc = W + (size_t)m0 * Kdim + kt * 64 + ldc;
        const __nv_bfloat16* bsrc = Bp + (size_t)n0 * Kdim + kt * 64 + ldc;
        uint32_t aDst = aU + (uint32_t)(st * GTILE) * 2;
        uint32_t bDst = bU + (uint32_t)(st * GTILE) * 2;
#pragma unroll
        for (int i = 0; i < 8; i++) {
            int r = ldr + i * 16;
            cp16(aDst + (r * GSTRIDE + ldc) * 2, wsrc + (size_t)r * Kdim);
            cp16(bDst + (r * GSTRIDE + ldc) * 2, bsrc + (size_t)r * Kdim);
        }
        CP_COMMIT();
    };

    int ktiles = Kdim >> 6;
    prefetch(0, 0);
    prefetch(1, 1);

    float acc[4][8][4] = {};
    int aRow = lane & 15, aK = (lane >> 4) * 8;
    int bRow = lane & 7,  bK = ((lane >> 3) & 1) * 8;
    int aOff[4], bOff[8];
#pragma unroll
    for (int mt = 0; mt < 4; mt++) aOff[mt] = (wm0 + mt * 16 + aRow) * GSTRIDE + aK;
#pragma unroll
    for (int nt = 0; nt < 8; nt++) bOff[nt] = (wn0 + nt * 8 + bRow) * GSTRIDE + bK;

    for (int kt = 0; kt < ktiles; kt++) {
        CP_WAIT1();
        __syncthreads();
        if (kt + 2 < ktiles) prefetch(kt + 2, (kt + 2) % 3);
        int st = kt % 3;
        uint32_t aB = aU + (uint32_t)(st * GTILE) * 2;
        uint32_t bB = bU + (uint32_t)(st * GTILE) * 2;
#pragma unroll
        for (int kk = 0; kk < 64; kk += 16) {
            uint32_t af[4][4], bf[8][2];
#pragma unroll
            for (int mt = 0; mt < 4; mt++)
                LDSM_X4(af[mt][0], af[mt][1], af[mt][2], af[mt][3],
                        aB + (uint32_t)(aOff[mt] + kk) * 2);
#pragma unroll
            for (int nt = 0; nt < 8; nt++)
                LDSM_X2(bf[nt][0], bf[nt][1], bB + (uint32_t)(bOff[nt] + kk) * 2);
#pragma unroll
            for (int mt = 0; mt < 4; mt++)
#pragma unroll
                for (int nt = 0; nt < 8; nt++)
                    MMA_BF16(acc[mt][nt], af[mt][0], af[mt][1], af[mt][2],
                             af[mt][3], bf[nt][0], bf[nt][1]);
        }
    }

    if (qTp) {
#pragma unroll
        for (int mt = 0; mt < 4; mt++)
#pragma unroll
            for (int nt = 0; nt < 8; nt++) {
                int r0 = m0 + wm0 + mt * 16 + gr;
                int cc = n0 + wn0 + nt * 8 + gc * 2;
                float bv0 = bias[r0], bv1 = bias[r0 + 8];
                float* c = acc[mt][nt];
#pragma unroll
                for (int e = 0; e < 4; e++) {
                    int m = r0 + ((e >> 1) << 3);
                    int n = cc + (e & 1);
                    float val = c[e] + ((e >> 1) ? bv1 : bv0);
                    int head = m / 192;
                    int r = m - head * 192;
                    size_t bh = (size_t)(bz * 8 + head);
                    if (r < 64)
                        qTp[(bh * 1024 + n) * 64 + r] = __float2bfloat16(val * 0.125f);
                    else if (r < 128)
                        kTp[(bh * 1024 + n) * 64 + (r - 64)] = __float2bfloat16(val);
                    else
                        vp[(bh * 64 + (r - 128)) * 1024 + n] = __float2bfloat16(val);
                }
            }
    } else {
        float* Cp = Cout + (size_t)bz * M * 1024;
        const float* Rp = resid + (size_t)bz * M * 1024;
#pragma unroll
        for (int mt = 0; mt < 4; mt++)
#pragma unroll
            for (int nt = 0; nt < 8; nt++) {
                int r0 = m0 + wm0 + mt * 16 + gr;
                int cc = n0 + wn0 + nt * 8 + gc * 2;
                float bv0 = bias[r0], bv1 = bias[r0 + 8];
                float* c = acc[mt][nt];
                size_t off0 = (size_t)r0 * 1024 + cc;
                size_t off1 = (size_t)(r0 + 8) * 1024 + cc;
                float2 r0v = *(const float2*)&Rp[off0];
                float2 r1v = *(const float2*)&Rp[off1];
                *(float2*)&Cp[off0] =
                    make_float2(c[0] + bv0 + r0v.x, c[1] + bv0 + r0v.y);
                *(float2*)&Cp[off1] =
                    make_float2(c[2] + bv1 + r1v.x, c[3] + bv1 + r1v.y);
            }
    }
}

// ---------------- BF16 flash attention: register-resident softmax ------------
extern __shared__ char attn_smem[];
__global__ __launch_bounds__(256, 2)
void attn_bf16_kernel(const __nv_bfloat16* __restrict__ qT,
                      const __nv_bfloat16* __restrict__ kT,
                      const __nv_bfloat16* __restrict__ vb,
                      __nv_bfloat16* __restrict__ aT) {
    __nv_bfloat16* Qt = (__nv_bfloat16*)attn_smem;   // [128][72] t x c
    __nv_bfloat16* Kt = Qt + 128 * 72;               // [64][72]  s x c
    __nv_bfloat16* Vs = Kt + 64 * 72;                // [64][72]  c x s

    int bh = blockIdx.y;
    int b = bh >> 3, h = bh & 7;
    int t0 = blockIdx.x * 128;
    const __nv_bfloat16* Qp = qT + (size_t)bh * 1024 * 64;
    const __nv_bfloat16* Kp = kT + (size_t)bh * 1024 * 64;
    const __nv_bfloat16* Vp = vb + (size_t)bh * 64 * 1024;

    int tid = threadIdx.x;
    int wid = tid >> 5, lane = tid & 31;
    int wm0 = wid * 16;
    int gr = lane >> 2, gc = lane & 3;
    int ldr = tid >> 3, ldc = (tid & 7) * 8;

#pragma unroll
    for (int it = 0; it < 4; it++) {
        int r = ldr + it * 32;
        *(uint4*)&Qt[r * 72 + ldc] = *(const uint4*)&Qp[(size_t)(t0 + r) * 64 + ldc];
    }

    uint4 kreg[2], vreg[2];
#pragma unroll
    for (int it = 0; it < 2; it++) {
        int r = ldr + it * 32;
        kreg[it] = *(const uint4*)&Kp[(size_t)r * 64 + ldc];
        vreg[it] = *(const uint4*)&Vp[(size_t)r * 1024 + ldc];
    }

    uint32_t qU = su32(Qt), kU = su32(Kt), vU = su32(Vs);
    int aRow = lane & 15, aK = (lane >> 4) * 8;
    int bRow = lane & 7,  bK = ((lane >> 3) & 1) * 8;
    int aOff = (wm0 + aRow) * 72 + aK;
    int bOff[8];
#pragma unroll
    for (int nt = 0; nt < 8; nt++) bOff[nt] = (nt * 8 + bRow) * 72 + bK;

    float O[8][4] = {};
    float m0 = -INFINITY, m1 = -INFINITY, l0 = 0.f, l1 = 0.f;

    for (int s0 = 0; s0 < 1024; s0 += 64) {
        __syncthreads();
#pragma unroll
        for (int it = 0; it < 2; it++) {
            int r = ldr + it * 32;
            *(uint4*)&Kt[r * 72 + ldc] = kreg[it];
            *(uint4*)&Vs[r * 72 + ldc] = vreg[it];
        }
        __syncthreads();
        if (s0 + 64 < 1024) {
            int sn = s0 + 64;
#pragma unroll
            for (int it = 0; it < 2; it++) {
                int r = ldr + it * 32;
                kreg[it] = *(const uint4*)&Kp[(size_t)(sn + r) * 64 + ldc];
                vreg[it] = *(const uint4*)&Vp[(size_t)r * 1024 + sn + ldc];
            }
        }

        float S[8][4] = {};
#pragma unroll
        for (int kk = 0; kk < 64; kk += 16) {
            uint32_t a0, a1, a2, a3;
            LDSM_X4(a0, a1, a2, a3, qU + (uint32_t)(aOff + kk) * 2);
#pragma unroll
            for (int nt = 0; nt < 8; nt++) {
                uint32_t b0, b1;
                LDSM_X2(b0, b1, kU + (uint32_t)(bOff[nt] + kk) * 2);
                MMA_BF16(S[nt], a0, a1, a2, a3, b0, b1);
            }
        }

        float mx0 = -INFINITY, mx1 = -INFINITY;
#pragma unroll
        for (int nt = 0; nt < 8; nt++) {
            mx0 = fmaxf(mx0, fmaxf(S[nt][0], S[nt][1]));
            mx1 = fmaxf(mx1, fmaxf(S[nt][2], S[nt][3]));
        }
        mx0 = fmaxf(mx0, __shfl_xor_sync(0xffffffffu, mx0, 1));
        mx0 = fmaxf(mx0, __shfl_xor_sync(0xffffffffu, mx0, 2));
        mx1 = fmaxf(mx1, __shfl_xor_sync(0xffffffffu, mx1, 1));
        mx1 = fmaxf(mx1, __shfl_xor_sync(0xffffffffu, mx1, 2));
        float mn0 = fmaxf(m0, mx0), mn1 = fmaxf(m1, mx1);
        float corr0 = __expf(m0 - mn0), corr1 = __expf(m1 - mn1);
        m0 = mn0; m1 = mn1;

        float rs0 = 0.f, rs1 = 0.f;
        uint32_t P[8][2];
#pragma unroll
        for (int nt = 0; nt < 8; nt++) {
            float p0 = __expf(S[nt][0] - mn0);
            float p1 = __expf(S[nt][1] - mn0);
            float p2 = __expf(S[nt][2] - mn1);
            float p3 = __expf(S[nt][3] - mn1);
            rs0 += p0 + p1; rs1 += p2 + p3;
            P[nt][0] = pack_bf16(p0, p1);
            P[nt][1] = pack_bf16(p2, p3);
        }
        rs0 += __shfl_xor_sync(0xffffffffu, rs0, 1);
        rs0 += __shfl_xor_sync(0xffffffffu, rs0, 2);
        rs1 += __shfl_xor_sync(0xffffffffu, rs1, 1);
        rs1 += __shfl_xor_sync(0xffffffffu, rs1, 2);
        l0 = l0 * corr0 + rs0;
        l1 = l1 * corr1 + rs1;

#pragma unroll
        for (int nt = 0; nt < 8; nt++) {
            O[nt][0] *= corr0; O[nt][1] *= corr0;
            O[nt][2] *= corr1; O[nt][3] *= corr1;
        }
#pragma unroll
        for (int j = 0; j < 4; j++) {
            uint32_t a0 = P[2 * j][0], a1 = P[2 * j][1];
            uint32_t a2 = P[2 * j + 1][0], a3 = P[2 * j + 1][1];
#pragma unroll
            for (int nt = 0; nt < 8; nt++) {
                uint32_t b0, b1;
                LDSM_X2(b0, b1, vU + (uint32_t)(bOff[nt] + 16 * j) * 2);
                MMA_BF16(O[nt], a0, a1, a2, a3, b0, b1);
            }
        }
    }

    {
        float inv0 = 1.f / l0, inv1 = 1.f / l1;
        __nv_bfloat16* ap = aT + ((size_t)b * 1024 + t0) * 512 + h * 64;
#pragma unroll
        for (int nt = 0; nt < 8; nt++) {
            int cc = nt * 8 + gc * 2;
            *(uint32_t*)&ap[(size_t)(wm0 + gr) * 512 + cc] =
                pack_bf16(O[nt][0] * inv0, O[nt][1] * inv0);
            *(uint32_t*)&ap[(size_t)(wm0 + gr + 8) * 512 + cc] =
                pack_bf16(O[nt][2] * inv1, O[nt][3] * inv1);
        }
    }
}

// ---------------- launch ----------------------------------------------------
extern "C" void kernel_launch(void* const* d_in, const int* in_sizes, int n_in,
                              void* d_out, int out_size) {
    const float* x      = (const float*)d_in[0];
    const float* gamma  = (const float*)d_in[1];
    const float* beta   = (const float*)d_in[2];
    const float* w_qkv  = (const float*)d_in[3];
    const float* b_qkv  = (const float*)d_in[4];
    const float* w_proj = (const float*)d_in[5];
    const float* b_proj = (const float*)d_in[6];
    float* out = (float*)d_out;

    __nv_bfloat16 *wqkv_p, *wproj_p, *hT_p, *qT_p, *kT_p, *v_p, *aT_p;
    cudaGetSymbolAddress((void**)&wqkv_p, g_wqkv);
    cudaGetSymbolAddress((void**)&wproj_p, g_wproj);
    cudaGetSymbolAddress((void**)&hT_p, g_hT);
    cudaGetSymbolAddress((void**)&qT_p, g_qT);
    cudaGetSymbolAddress((void**)&kT_p, g_kT);
    cudaGetSymbolAddress((void**)&v_p, g_v);
    cudaGetSymbolAddress((void**)&aT_p, g_aT);

    // 0) convert weights to bf16
    f2bf_kernel<<<768, 256>>>(w_qkv, wqkv_p, 196608);
    f2bf_kernel<<<256, 256>>>(w_proj, wproj_p, 65536);

    // 1) GroupNorm -> hT bf16 [b][t][c]
    groupnorm_t_kernel<<<8 * 32, 256>>>(x, gamma, beta, hT_p);

    // 2) QKV GEMM (bf16, 64x64 warp tiles): q(scaled)/k/v -> bf16 buffers
    cudaFuncSetAttribute(gemm_bf16_async,
                         cudaFuncAttributeMaxDynamicSharedMemorySize, 110592);
    gemm_bf16_async<<<dim3(8, 12, 8), 128, 110592>>>(
        wqkv_p, hT_p, b_qkv, nullptr, nullptr, qT_p, kT_p, v_p, 1536, 512);

    // 3) Attention (register-resident softmax) -> aT bf16
    attn_bf16_kernel<<<dim3(8, 64), 256, 36864>>>(qT_p, kT_p, v_p, aT_p);

    // 4) Proj GEMM + bias + residual -> fp32 out
    gemm_bf16_async<<<dim3(8, 4, 8), 128, 110592>>>(
        wproj_p, aT_p, b_proj, x, out, nullptr, nullptr, nullptr, 512, 512);
}

// round 15
// speedup vs baseline: 1.5779x; 1.5779x over previous
#include <cuda_runtime.h>
#include <cuda_bf16.h>
#include <math.h>
#include <stdint.h>

// ---------------- scratch (static device globals; no allocation) ------------
__device__ __nv_bfloat16 g_wqkv[1536 * 512];     // w_qkv bf16
__device__ __nv_bfloat16 g_wproj[512 * 512];     // w_proj bf16
__device__ __nv_bfloat16 g_hT[8 * 1024 * 512];   // groupnorm out [b][t][c]
__device__ __nv_bfloat16 g_qT[64 * 1024 * 64];   // Q [bh][t][c] (pre-scaled 1/8)
__device__ __nv_bfloat16 g_kT[64 * 1024 * 64];   // K [bh][s][c]
__device__ __nv_bfloat16 g_v[64 * 64 * 1024];    // V [bh][c][t]
__device__ __nv_bfloat16 g_aT[8 * 1024 * 512];   // attention out [b][t][c]

__device__ __forceinline__ uint32_t pack_bf16(float lo, float hi) {
    uint32_t r;
    asm("cvt.rn.bf16x2.f32 %0, %1, %2;" : "=r"(r) : "f"(hi), "f"(lo));
    return r;
}
__device__ __forceinline__ uint32_t su32(const void* p) {
    return (uint32_t)__cvta_generic_to_shared(p);
}
__device__ __forceinline__ void cp16(uint32_t dst, const void* src) {
    asm volatile("cp.async.ca.shared.global [%0], [%1], 16;" :: "r"(dst), "l"(src));
}
#define CP_COMMIT() asm volatile("cp.async.commit_group;")
#define CP_WAIT1()  asm volatile("cp.async.wait_group 1;")

#define MMA_BF16(c, a0, a1, a2, a3, b0, b1)                                   \
    asm volatile(                                                             \
        "mma.sync.aligned.m16n8k16.row.col.f32.bf16.bf16.f32 "                \
        "{%0,%1,%2,%3}, {%4,%5,%6,%7}, {%8,%9}, {%0,%1,%2,%3};"               \
        : "+f"((c)[0]), "+f"((c)[1]), "+f"((c)[2]), "+f"((c)[3])              \
        : "r"(a0), "r"(a1), "r"(a2), "r"(a3), "r"(b0), "r"(b1))

#define LDSM_X4(r0, r1, r2, r3, addr)                                         \
    asm volatile("ldmatrix.sync.aligned.m8n8.x4.shared.b16 {%0,%1,%2,%3}, [%4];" \
                 : "=r"(r0), "=r"(r1), "=r"(r2), "=r"(r3) : "r"(addr))

// ---------------- fp32 -> bf16 convert (weights) ----------------------------
__global__ void f2bf_kernel(const float* __restrict__ in,
                            __nv_bfloat16* __restrict__ out, int n4) {
    int i = blockIdx.x * 256 + threadIdx.x;
    if (i < n4) {
        float4 v = ((const float4*)in)[i];
        *(uint2*)&out[i * 4] =
            make_uint2(pack_bf16(v.x, v.y), pack_bf16(v.z, v.w));
    }
}

// ---------------- GroupNorm (writes transposed bf16 hT [b][t][c]) -----------
__global__ void groupnorm_t_kernel(const float* __restrict__ x,
                                   const float* __restrict__ gamma,
                                   const float* __restrict__ beta,
                                   __nv_bfloat16* __restrict__ hT) {
    int b = blockIdx.x >> 5;
    int g = blockIdx.x & 31;
    const float* xp = x + ((size_t)b * 512 + g * 16) * 1024;
    int tid = threadIdx.x;

    float s = 0.f, ss = 0.f;
    for (int e = tid; e < 16 * 1024; e += 256) {
        float v = xp[e];
        s += v; ss += v * v;
    }
    __shared__ float rs[256], rss[256];
    __shared__ float Ts[64][20];
    rs[tid] = s; rss[tid] = ss;
    __syncthreads();
    for (int o = 128; o > 0; o >>= 1) {
        if (tid < o) { rs[tid] += rs[tid + o]; rss[tid] += rss[tid + o]; }
        __syncthreads();
    }
    float mean = rs[0] * (1.f / 16384.f);
    float var  = rss[0] * (1.f / 16384.f) - mean * mean;
    float inv  = rsqrtf(var + 1e-5f);

    int cl = tid >> 4;
    int tw4 = (tid & 15) * 4;
    float scale = inv * gamma[g * 16 + cl];
    float shift = beta[g * 16 + cl] - mean * scale;
    __nv_bfloat16* hTb = hT + (size_t)b * 1024 * 512 + g * 16;
    int tr = tid >> 2, q = tid & 3;

    for (int t0 = 0; t0 < 1024; t0 += 64) {
        float4 v = *(const float4*)&xp[cl * 1024 + t0 + tw4];
        Ts[tw4 + 0][cl] = v.x * scale + shift;
        Ts[tw4 + 1][cl] = v.y * scale + shift;
        Ts[tw4 + 2][cl] = v.z * scale + shift;
        Ts[tw4 + 3][cl] = v.w * scale + shift;
        __syncthreads();
        *(uint2*)&hTb[(size_t)(t0 + tr) * 512 + q * 4] =
            make_uint2(pack_bf16(Ts[tr][q * 4 + 0], Ts[tr][q * 4 + 1]),
                       pack_bf16(Ts[tr][q * 4 + 2], Ts[tr][q * 4 + 3]));
        __syncthreads();
    }
}

// ---------------- BF16 GEMM: cp.async 3-stage + ldmatrix (x4 B-frags) --------
// Block 128x128, BK=64, 256 threads (8 warps 2x4), warp tile 64x32.
#define GSTRIDE 72
#define GTILE (128 * GSTRIDE)
extern __shared__ __nv_bfloat16 dyn_smem[];

__global__ __launch_bounds__(256, 2)
void gemm_bf16_async(const __nv_bfloat16* __restrict__ W,
                     const __nv_bfloat16* __restrict__ BT,
                     const float* __restrict__ bias,
                     const float* __restrict__ resid,
                     float* __restrict__ Cout,
                     __nv_bfloat16* __restrict__ qTp,
                     __nv_bfloat16* __restrict__ kTp,
                     __nv_bfloat16* __restrict__ vp,
                     int M, int Kdim) {
    __nv_bfloat16* As = dyn_smem;
    __nv_bfloat16* Bs = dyn_smem + 3 * GTILE;

    int bz = blockIdx.z;
    const __nv_bfloat16* Bp = BT + (size_t)bz * 1024 * Kdim;

    int m0 = blockIdx.y * 128, n0 = blockIdx.x * 128;
    int tid = threadIdx.x;
    int wid = tid >> 5, lane = tid & 31;
    int warp_m = wid >> 2, warp_n = wid & 3;
    int wm0 = warp_m * 64, wn0 = warp_n * 32;
    int gr = lane >> 2, gc = lane & 3;

    int ldr = tid >> 3;
    int ldc = (tid & 7) * 8;
    uint32_t aU = su32(As), bU = su32(Bs);

    auto prefetch = [&](int kt, int st) {
        const __nv_bfloat16* wsrc = W + (size_t)m0 * Kdim + kt * 64 + ldc;
        const __nv_bfloat16* bsrc = Bp + (size_t)n0 * Kdim + kt * 64 + ldc;
        uint32_t aDst = aU + (uint32_t)(st * GTILE) * 2;
        uint32_t bDst = bU + (uint32_t)(st * GTILE) * 2;
#pragma unroll
        for (int i = 0; i < 4; i++) {
            int r = ldr + i * 32;
            cp16(aDst + (r * GSTRIDE + ldc) * 2, wsrc + (size_t)r * Kdim);
            cp16(bDst + (r * GSTRIDE + ldc) * 2, bsrc + (size_t)r * Kdim);
        }
        CP_COMMIT();
    };

    int ktiles = Kdim >> 6;
    prefetch(0, 0);
    prefetch(1, 1);

    float acc[4][4][4] = {};
    int aRow = lane & 15, aK = (lane >> 4) * 8;
    int aOff[4];
#pragma unroll
    for (int mt = 0; mt < 4; mt++) aOff[mt] = (wm0 + mt * 16 + aRow) * GSTRIDE + aK;
    // B x4 frag address: two adjacent 8-row n-tiles per ldsm
    int bRow4 = ((lane >> 4) << 3) + (lane & 7);
    int bK4 = ((lane >> 3) & 1) * 8;
    int bOff4[2];
#pragma unroll
    for (int j = 0; j < 2; j++) bOff4[j] = (wn0 + j * 16 + bRow4) * GSTRIDE + bK4;

    for (int kt = 0; kt < ktiles; kt++) {
        CP_WAIT1();
        __syncthreads();
        if (kt + 2 < ktiles) prefetch(kt + 2, (kt + 2) % 3);
        int st = kt % 3;
        uint32_t aB = aU + (uint32_t)(st * GTILE) * 2;
        uint32_t bB = bU + (uint32_t)(st * GTILE) * 2;
#pragma unroll
        for (int kk = 0; kk < 64; kk += 16) {
            uint32_t af[4][4], bf[4][2];
#pragma unroll
            for (int mt = 0; mt < 4; mt++)
                LDSM_X4(af[mt][0], af[mt][1], af[mt][2], af[mt][3],
                        aB + (uint32_t)(aOff[mt] + kk) * 2);
#pragma unroll
            for (int j = 0; j < 2; j++)
                LDSM_X4(bf[2 * j][0], bf[2 * j][1], bf[2 * j + 1][0],
                        bf[2 * j + 1][1], bB + (uint32_t)(bOff4[j] + kk) * 2);
#pragma unroll
            for (int mt = 0; mt < 4; mt++)
#pragma unroll
                for (int nt = 0; nt < 4; nt++)
                    MMA_BF16(acc[mt][nt], af[mt][0], af[mt][1], af[mt][2],
                             af[mt][3], bf[nt][0], bf[nt][1]);
        }
    }

    if (qTp) {
#pragma unroll
        for (int mt = 0; mt < 4; mt++)
#pragma unroll
            for (int nt = 0; nt < 4; nt++) {
                int r0 = m0 + wm0 + mt * 16 + gr;
                int cc = n0 + wn0 + nt * 8 + gc * 2;
                float bv0 = bias[r0], bv1 = bias[r0 + 8];
                float* c = acc[mt][nt];
#pragma unroll
                for (int e = 0; e < 4; e++) {
                    int m = r0 + ((e >> 1) << 3);
                    int n = cc + (e & 1);
                    float val = c[e] + ((e >> 1) ? bv1 : bv0);
                    int head = m / 192;
                    int r = m - head * 192;
                    size_t bh = (size_t)(bz * 8 + head);
                    if (r < 64)
                        qTp[(bh * 1024 + n) * 64 + r] = __float2bfloat16(val * 0.125f);
                    else if (r < 128)
                        kTp[(bh * 1024 + n) * 64 + (r - 64)] = __float2bfloat16(val);
                    else
                        vp[(bh * 64 + (r - 128)) * 1024 + n] = __float2bfloat16(val);
                }
            }
    } else {
        float* Cp = Cout + (size_t)bz * M * 1024;
        const float* Rp = resid + (size_t)bz * M * 1024;
#pragma unroll
        for (int mt = 0; mt < 4; mt++)
#pragma unroll
            for (int nt = 0; nt < 4; nt++) {
                int r0 = m0 + wm0 + mt * 16 + gr;
                int cc = n0 + wn0 + nt * 8 + gc * 2;
                float bv0 = bias[r0], bv1 = bias[r0 + 8];
                float* c = acc[mt][nt];
                size_t off0 = (size_t)r0 * 1024 + cc;
                size_t off1 = (size_t)(r0 + 8) * 1024 + cc;
                float2 r0v = *(const float2*)&Rp[off0];
                float2 r1v = *(const float2*)&Rp[off1];
                *(float2*)&Cp[off0] =
                    make_float2(c[0] + bv0 + r0v.x, c[1] + bv0 + r0v.y);
                *(float2*)&Cp[off1] =
                    make_float2(c[2] + bv1 + r1v.x, c[3] + bv1 + r1v.y);
            }
    }
}

// ---------------- BF16 flash attention: register softmax + x4 B-frags --------
extern __shared__ char attn_smem[];
__global__ __launch_bounds__(256, 2)
void attn_bf16_kernel(const __nv_bfloat16* __restrict__ qT,
                      const __nv_bfloat16* __restrict__ kT,
                      const __nv_bfloat16* __restrict__ vb,
                      __nv_bfloat16* __restrict__ aT) {
    __nv_bfloat16* Qt = (__nv_bfloat16*)attn_smem;   // [128][72] t x c
    __nv_bfloat16* Kt = Qt + 128 * 72;               // [64][72]  s x c
    __nv_bfloat16* Vs = Kt + 64 * 72;                // [64][72]  c x s

    int bh = blockIdx.y;
    int b = bh >> 3, h = bh & 7;
    int t0 = blockIdx.x * 128;
    const __nv_bfloat16* Qp = qT + (size_t)bh * 1024 * 64;
    const __nv_bfloat16* Kp = kT + (size_t)bh * 1024 * 64;
    const __nv_bfloat16* Vp = vb + (size_t)bh * 64 * 1024;

    int tid = threadIdx.x;
    int wid = tid >> 5, lane = tid & 31;
    int wm0 = wid * 16;
    int gr = lane >> 2, gc = lane & 3;
    int ldr = tid >> 3, ldc = (tid & 7) * 8;

#pragma unroll
    for (int it = 0; it < 4; it++) {
        int r = ldr + it * 32;
        *(uint4*)&Qt[r * 72 + ldc] = *(const uint4*)&Qp[(size_t)(t0 + r) * 64 + ldc];
    }

    uint4 kreg[2], vreg[2];
#pragma unroll
    for (int it = 0; it < 2; it++) {
        int r = ldr + it * 32;
        kreg[it] = *(const uint4*)&Kp[(size_t)r * 64 + ldc];
        vreg[it] = *(const uint4*)&Vp[(size_t)r * 1024 + ldc];
    }

    uint32_t qU = su32(Qt), kU = su32(Kt), vU = su32(Vs);
    int aRow = lane & 15, aK = (lane >> 4) * 8;
    int aOff = (wm0 + aRow) * 72 + aK;
    // x4 B frags: two adjacent 8-row n-tiles per ldsm
    int bRow4 = ((lane >> 4) << 3) + (lane & 7);
    int bK4 = ((lane >> 3) & 1) * 8;
    int bOff4[4];
#pragma unroll
    for (int j = 0; j < 4; j++) bOff4[j] = (j * 16 + bRow4) * 72 + bK4;

    float O[8][4] = {};
    float m0 = -INFINITY, m1 = -INFINITY, l0 = 0.f, l1 = 0.f;

    for (int s0 = 0; s0 < 1024; s0 += 64) {
        __syncthreads();
#pragma unroll
        for (int it = 0; it < 2; it++) {
            int r = ldr + it * 32;
            *(uint4*)&Kt[r * 72 + ldc] = kreg[it];
            *(uint4*)&Vs[r * 72 + ldc] = vreg[it];
        }
        __syncthreads();
        if (s0 + 64 < 1024) {
            int sn = s0 + 64;
#pragma unroll
            for (int it = 0; it < 2; it++) {
                int r = ldr + it * 32;
                kreg[it] = *(const uint4*)&Kp[(size_t)(sn + r) * 64 + ldc];
                vreg[it] = *(const uint4*)&Vp[(size_t)r * 1024 + sn + ldc];
            }
        }

        float S[8][4] = {};
#pragma unroll
        for (int kk = 0; kk < 64; kk += 16) {
            uint32_t a0, a1, a2, a3;
            LDSM_X4(a0, a1, a2, a3, qU + (uint32_t)(aOff + kk) * 2);
#pragma unroll
            for (int j = 0; j < 4; j++) {
                uint32_t b0, b1, b2, b3;
                LDSM_X4(b0, b1, b2, b3, kU + (uint32_t)(bOff4[j] + kk) * 2);
                MMA_BF16(S[2 * j], a0, a1, a2, a3, b0, b1);
                MMA_BF16(S[2 * j + 1], a0, a1, a2, a3, b2, b3);
            }
        }

        float mx0 = -INFINITY, mx1 = -INFINITY;
#pragma unroll
        for (int nt = 0; nt < 8; nt++) {
            mx0 = fmaxf(mx0, fmaxf(S[nt][0], S[nt][1]));
            mx1 = fmaxf(mx1, fmaxf(S[nt][2], S[nt][3]));
        }
        mx0 = fmaxf(mx0, __shfl_xor_sync(0xffffffffu, mx0, 1));
        mx0 = fmaxf(mx0, __shfl_xor_sync(0xffffffffu, mx0, 2));
        mx1 = fmaxf(mx1, __shfl_xor_sync(0xffffffffu, mx1, 1));
        mx1 = fmaxf(mx1, __shfl_xor_sync(0xffffffffu, mx1, 2));
        float mn0 = fmaxf(m0, mx0), mn1 = fmaxf(m1, mx1);
        float corr0 = __expf(m0 - mn0), corr1 = __expf(m1 - mn1);
        m0 = mn0; m1 = mn1;

        float rs0 = 0.f, rs1 = 0.f;
        uint32_t P[8][2];
#pragma unroll
        for (int nt = 0; nt < 8; nt++) {
            float p0 = __expf(S[nt][0] - mn0);
            float p1 = __expf(S[nt][1] - mn0);
            float p2 = __expf(S[nt][2] - mn1);
            float p3 = __expf(S[nt][3] - mn1);
            rs0 += p0 + p1; rs1 += p2 + p3;
            P[nt][0] = pack_bf16(p0, p1);
            P[nt][1] = pack_bf16(p2, p3);
        }
        rs0 += __shfl_xor_sync(0xffffffffu, rs0, 1);
        rs0 += __shfl_xor_sync(0xffffffffu, rs0, 2);
        rs1 += __shfl_xor_sync(0xffffffffu, rs1, 1);
        rs1 += __shfl_xor_sync(0xffffffffu, rs1, 2);
        l0 = l0 * corr0 + rs0;
        l1 = l1 * corr1 + rs1;

#pragma unroll
        for (int nt = 0; nt < 8; nt++) {
            O[nt][0] *= corr0; O[nt][1] *= corr0;
            O[nt][2] *= corr1; O[nt][3] *= corr1;
        }
#pragma unroll
        for (int j4 = 0; j4 < 4; j4++) {
            uint32_t a0 = P[2 * j4][0], a1 = P[2 * j4][1];
            uint32_t a2 = P[2 * j4 + 1][0], a3 = P[2 * j4 + 1][1];
#pragma unroll
            for (int j = 0; j < 4; j++) {
                uint32_t b0, b1, b2, b3;
                LDSM_X4(b0, b1, b2, b3, vU + (uint32_t)(bOff4[j] + 16 * j4) * 2);
                MMA_BF16(O[2 * j], a0, a1, a2, a3, b0, b1);
                MMA_BF16(O[2 * j + 1], a0, a1, a2, a3, b2, b3);
            }
        }
    }

    {
        float inv0 = 1.f / l0, inv1 = 1.f / l1;
        __nv_bfloat16* ap = aT + ((size_t)b * 1024 + t0) * 512 + h * 64;
#pragma unroll
        for (int nt = 0; nt < 8; nt++) {
            int cc = nt * 8 + gc * 2;
            *(uint32_t*)&ap[(size_t)(wm0 + gr) * 512 + cc] =
                pack_bf16(O[nt][0] * inv0, O[nt][1] * inv0);
            *(uint32_t*)&ap[(size_t)(wm0 + gr + 8) * 512 + cc] =
                pack_bf16(O[nt][2] * inv1, O[nt][3] * inv1);
        }
    }
}

// ---------------- launch ----------------------------------------------------
extern "C" void kernel_launch(void* const* d_in, const int* in_sizes, int n_in,
                              void* d_out, int out_size) {
    const float* x      = (const float*)d_in[0];
    const float* gamma  = (const float*)d_in[1];
    const float* beta   = (const float*)d_in[2];
    const float* w_qkv  = (const float*)d_in[3];
    const float* b_qkv  = (const float*)d_in[4];
    const float* w_proj = (const float*)d_in[5];
    const float* b_proj = (const float*)d_in[6];
    float* out = (float*)d_out;

    __nv_bfloat16 *wqkv_p, *wproj_p, *hT_p, *qT_p, *kT_p, *v_p, *aT_p;
    cudaGetSymbolAddress((void**)&wqkv_p, g_wqkv);
    cudaGetSymbolAddress((void**)&wproj_p, g_wproj);
    cudaGetSymbolAddress((void**)&hT_p, g_hT);
    cudaGetSymbolAddress((void**)&qT_p, g_qT);
    cudaGetSymbolAddress((void**)&kT_p, g_kT);
    cudaGetSymbolAddress((void**)&v_p, g_v);
    cudaGetSymbolAddress((void**)&aT_p, g_aT);

    // 0) convert weights to bf16
    f2bf_kernel<<<768, 256>>>(w_qkv, wqkv_p, 196608);
    f2bf_kernel<<<256, 256>>>(w_proj, wproj_p, 65536);

    // 1) GroupNorm -> hT bf16 [b][t][c]
    groupnorm_t_kernel<<<8 * 32, 256>>>(x, gamma, beta, hT_p);

    // 2) QKV GEMM (bf16, async): q(scaled)/k/v -> bf16 buffers
    cudaFuncSetAttribute(gemm_bf16_async,
                         cudaFuncAttributeMaxDynamicSharedMemorySize, 110592);
    gemm_bf16_async<<<dim3(8, 12, 8), 256, 110592>>>(
        wqkv_p, hT_p, b_qkv, nullptr, nullptr, qT_p, kT_p, v_p, 1536, 512);

    // 3) Attention (register-resident softmax) -> aT bf16
    attn_bf16_kernel<<<dim3(8, 64), 256, 36864>>>(qT_p, kT_p, v_p, aT_p);

    // 4) Proj GEMM + bias + residual -> fp32 out
    gemm_bf16_async<<<dim3(8, 4, 8), 256, 110592>>>(
        wproj_p, aT_p, b_proj, x, out, nullptr, nullptr, nullptr, 512, 512);
}